// round 14
// baseline (speedup 1.0000x reference)
#include <cuda_runtime.h>
#include <cuda_bf16.h>
#include <math.h>

// Problem constants (fixed by the dataset)
#define B   32
#define H   16
#define D   128
#define KV  2048
#define E   2048          // H*D
#define E3  6144          // 3*E
#define KV1 2049          // KV+1
#define KV1P 2052         // KV1 padded (keeps smem 16B-aligned)

// Scratch (device globals: allocation-free rule)
__device__ __align__(16) float g_qkv[B * E3];   // QKV projection result (B, 3E)
__device__ __align__(16) float g_ctx[B * E];    // attention context (B, E)

// ---- packed f32x2 helpers (sm_103a FFMA2 via PTX) -------------------------
__device__ __forceinline__ unsigned long long fma2(unsigned long long a,
                                                   unsigned long long b,
                                                   unsigned long long c)
{
    unsigned long long d;
    asm("fma.rn.f32x2 %0, %1, %2, %3;" : "=l"(d) : "l"(a), "l"(b), "l"(c));
    return d;
}
__device__ __forceinline__ void unpack2(unsigned long long a, float& lo, float& hi)
{
    asm("mov.b64 {%0, %1}, %2;" : "=f"(lo), "=f"(hi) : "l"(a));
}

// ---------------------------------------------------------------------------
// Init: seed atomic-accumulated outputs with bias; emit mask_new.
// ---------------------------------------------------------------------------
__global__ void init_kernel(const float* __restrict__ bqkv,
                            const float* __restrict__ bo,
                            const float* __restrict__ mask,
                            float* __restrict__ qkv,
                            float* __restrict__ outO,
                            float* __restrict__ outmask)
{
    const int i = blockIdx.x * blockDim.x + threadIdx.x;
    const int stride = gridDim.x * blockDim.x;
    for (int j = i; j < B * E3; j += stride) qkv[j] = bqkv[j % E3];
    for (int j = i; j < B * E;  j += stride) outO[j] = bo[j & (E - 1)];
    for (int j = i; j < B * KV1; j += stride) {
        int b = j / KV1, k = j - b * KV1;
        outmask[j] = (k == KV) ? 1.0f : mask[b * KV + k];
    }
}

// ---------------------------------------------------------------------------
// Split-K skinny GEMM v6 (FFMA2, row-split for occupancy):
// Y[rows, N] += X @ W. grid = (N/512, K/GK, 2), 256 threads.
// Thread = 2 adjacent columns x 16 rows (blockIdx.z selects row half).
// ~60 regs -> 4 CTAs/SM (32 warps) hides LDG latency by occupancy.
// ---------------------------------------------------------------------------
template <int GK>
__global__ void __launch_bounds__(256, 4)
gemm32_v6(const float* __restrict__ X,
          const float* __restrict__ W,
          float* __restrict__ Y,
          int K, int N)
{
    __shared__ __align__(16) float2 xs2[16][GK];   // (x,x) duplicated pairs

    const int tid  = threadIdx.x;
    const int col2 = blockIdx.x * 512 + tid * 2;
    const int k0   = blockIdx.y * GK;
    const int r0   = blockIdx.z * 16;              // row half

    // stage X[r0:r0+16][k0:k0+GK] duplicated: xs2[row][k] = (x, x)
    #pragma unroll
    for (int f = tid; f < 16 * GK / 4; f += 256) {
        const int row = f / (GK / 4);
        const int kq  = f % (GK / 4);
        const float4 v = *(const float4*)(X + (size_t)(r0 + row) * K + k0 + kq * 4);
        xs2[row][kq * 4 + 0] = make_float2(v.x, v.x);
        xs2[row][kq * 4 + 1] = make_float2(v.y, v.y);
        xs2[row][kq * 4 + 2] = make_float2(v.z, v.z);
        xs2[row][kq * 4 + 3] = make_float2(v.w, v.w);
    }
    __syncthreads();

    unsigned long long acc2[16];
    #pragma unroll
    for (int r = 0; r < 16; r++) acc2[r] = 0ull;

    const unsigned long long* Wp =
        (const unsigned long long*)(W + (size_t)k0 * N + col2);
    const size_t wstride = (size_t)N / 2;   // in ull units

    #pragma unroll 2
    for (int kk = 0; kk < GK; kk += 8) {
        unsigned long long wv2[8];
        #pragma unroll
        for (int j = 0; j < 8; j++) wv2[j] = __ldcs(Wp + (size_t)(kk + j) * wstride);
        #pragma unroll
        for (int r = 0; r < 16; r++) {
            const ulonglong2 xa = *(const ulonglong2*)&xs2[r][kk + 0];
            const ulonglong2 xb = *(const ulonglong2*)&xs2[r][kk + 2];
            const ulonglong2 xc = *(const ulonglong2*)&xs2[r][kk + 4];
            const ulonglong2 xd = *(const ulonglong2*)&xs2[r][kk + 6];
            unsigned long long a = acc2[r];
            a = fma2(xa.x, wv2[0], a);
            a = fma2(xa.y, wv2[1], a);
            a = fma2(xb.x, wv2[2], a);
            a = fma2(xb.y, wv2[3], a);
            a = fma2(xc.x, wv2[4], a);
            a = fma2(xc.y, wv2[5], a);
            a = fma2(xd.x, wv2[6], a);
            a = fma2(xd.y, wv2[7], a);
            acc2[r] = a;
        }
    }

    float* Yc = Y + (size_t)r0 * N + col2;
    #pragma unroll
    for (int r = 0; r < 16; r++) {
        float lo, hi;
        unpack2(acc2[r], lo, hi);
        atomicAdd(Yc + (size_t)r * N + 0, lo);
        atomicAdd(Yc + (size_t)r * N + 1, hi);
    }
}

// ---------------------------------------------------------------------------
// Fused attention + KV-cache concat (R10/R8 proven body).
// One block per (b, h). 256 threads.
// ---------------------------------------------------------------------------
__global__ void attn_kernel(const float* __restrict__ kcache,
                            const float* __restrict__ vcache,
                            const float* __restrict__ mask,
                            float* __restrict__ out_Kc,
                            float* __restrict__ out_Vc)
{
    __shared__ __align__(16) float q_sm[D];
    __shared__ __align__(16) float sc[KV1P];
    __shared__ __align__(16) float red[20];
    __shared__ __align__(16) float cpart[8][D];

    const int tid = threadIdx.x;
    const int w   = tid >> 5;
    const int l   = tid & 31;
    const int b   = blockIdx.x >> 4;
    const int h   = blockIdx.x & 15;
    const float scale = 0.08838834764831845f;   // 1/sqrt(128)

    const float* mrow = mask + (size_t)b * KV;

    if (tid < D) q_sm[tid] = g_qkv[(size_t)b * E3 + h * D + tid];
    __syncthreads();

    const float4 qf = *(const float4*)&q_sm[l * 4];

    const size_t bh = (size_t)b * H + h;
    const float4* Kin  = (const float4*)(kcache + bh * KV * D);
    float4*       Kout = (float4*)(out_Kc + bh * (size_t)KV1 * D);

    // ---- Pass 1: scores + Kc copy. Warp w does keys [kb, kb+8) ----
    for (int kb = w * 8; kb < KV; kb += 64) {
        float4 a[8];
        #pragma unroll
        for (int j = 0; j < 8; j++) a[j] = Kin[(size_t)(kb + j) * 32 + l];
        #pragma unroll
        for (int j = 0; j < 8; j++) Kout[(size_t)(kb + j) * 32 + l] = a[j];

        float dd[8];
        #pragma unroll
        for (int j = 0; j < 8; j++)
            dd[j] = a[j].x * qf.x + a[j].y * qf.y + a[j].z * qf.z + a[j].w * qf.w;
        #pragma unroll
        for (int j = 0; j < 8; j++) {
            #pragma unroll
            for (int off = 16; off > 0; off >>= 1)
                dd[j] += __shfl_xor_sync(0xFFFFFFFFu, dd[j], off);
        }
        if (l < 8) {
            float dv = dd[l];
            float m  = mrow[kb + l];
            sc[kb + l] = (m == 0.0f) ? -1e30f : dv * scale;
        }
    }

    // new key: from qkv scratch, also write Kc row 2048
    if (w == 0) {
        float4 kn = *(const float4*)&g_qkv[(size_t)b * E3 + E + h * D + l * 4];
        Kout[(size_t)KV * 32 + l] = kn;
        float dn = kn.x * qf.x + kn.y * qf.y + kn.z * qf.z + kn.w * qf.w;
        #pragma unroll
        for (int off = 16; off > 0; off >>= 1)
            dn += __shfl_xor_sync(0xFFFFFFFFu, dn, off);
        if (l == 0) sc[KV] = dn * scale;   // new token never masked
    }
    __syncthreads();

    // ---- Softmax over sc[0..2048] ----
    float mx = -1e30f;
    for (int k = tid; k < KV1; k += 256) mx = fmaxf(mx, sc[k]);
    #pragma unroll
    for (int off = 16; off > 0; off >>= 1)
        mx = fmaxf(mx, __shfl_xor_sync(0xFFFFFFFFu, mx, off));
    if (l == 0) red[w] = mx;
    __syncthreads();
    if (tid == 0) {
        float m = red[0];
        #pragma unroll
        for (int i = 1; i < 8; i++) m = fmaxf(m, red[i]);
        red[0] = m;
    }
    __syncthreads();
    const float M = red[0];

    float ls = 0.f;
    for (int k = tid; k < KV1; k += 256) {
        float e = __expf(sc[k] - M);
        sc[k] = e;
        ls += e;
    }
    #pragma unroll
    for (int off = 16; off > 0; off >>= 1)
        ls += __shfl_xor_sync(0xFFFFFFFFu, ls, off);
    if (l == 0) red[8 + w] = ls;
    __syncthreads();
    if (tid == 0) {
        float s = 0.f;
        #pragma unroll
        for (int i = 0; i < 8; i++) s += red[8 + i];
        red[16] = 1.0f / s;
    }
    __syncthreads();

    // ---- Pass 2: ctx + Vc copy. Warp w owns keys [w*256, w*256+256) ----
    const float4* Vin  = (const float4*)(vcache + bh * KV * D);
    float4*       Vout = (float4*)(out_Vc + bh * (size_t)KV1 * D);

    float4 acc = make_float4(0.f, 0.f, 0.f, 0.f);
    const int kstart = w * 256;
    for (int k = kstart; k < kstart + 256; k += 8) {
        float4 v[8];
        #pragma unroll
        for (int j = 0; j < 8; j++) v[j] = Vin[(size_t)(k + j) * 32 + l];
        #pragma unroll
        for (int j = 0; j < 8; j++) Vout[(size_t)(k + j) * 32 + l] = v[j];
        #pragma unroll
        for (int j = 0; j < 8; j++) {
            const float p = sc[k + j];
            acc.x += p * v[j].x; acc.y += p * v[j].y;
            acc.z += p * v[j].z; acc.w += p * v[j].w;
        }
    }
    if (w == 7) {
        float4 vn = *(const float4*)&g_qkv[(size_t)b * E3 + 2 * E + h * D + l * 4];
        Vout[(size_t)KV * 32 + l] = vn;
        float p = sc[KV];
        acc.x += p * vn.x; acc.y += p * vn.y; acc.z += p * vn.z; acc.w += p * vn.w;
    }
    *(float4*)&cpart[w][l * 4] = acc;
    __syncthreads();

    if (tid < D) {
        float s = 0.f;
        #pragma unroll
        for (int i = 0; i < 8; i++) s += cpart[i][tid];
        g_ctx[(size_t)b * E + h * D + tid] = s * red[16];
    }
}

// ---------------------------------------------------------------------------
extern "C" void kernel_launch(void* const* d_in, const int* in_sizes, int n_in,
                              void* d_out, int out_size)
{
    const float* X      = (const float*)d_in[0];
    const float* kcache = (const float*)d_in[1];
    const float* vcache = (const float*)d_in[2];
    const float* mask   = (const float*)d_in[3];
    const float* Wqkv   = (const float*)d_in[4];
    const float* bqkv   = (const float*)d_in[5];
    const float* Wo     = (const float*)d_in[6];
    const float* bo     = (const float*)d_in[7];

    float* out_O  = (float*)d_out;                              // (B, 1, E)
    float* out_Kc = out_O  + (size_t)B * E;                     // (B, H, KV1, D)
    float* out_Vc = out_Kc + (size_t)B * H * KV1 * D;           // (B, H, KV1, D)
    float* out_mk = out_Vc + (size_t)B * H * KV1 * D;           // (B, KV1)

    float* qkv;  cudaGetSymbolAddress((void**)&qkv,  g_qkv);
    float* ctx;  cudaGetSymbolAddress((void**)&ctx,  g_ctx);

    // 0) Seed outputs with bias (atomics accumulate on top), emit mask_new
    init_kernel<<<256, 256>>>(bqkv, bo, mask, qkv, out_O, out_mk);

    // 1) QKV projection: FFMA2 row-split gemm, GK=64 -> (12, 32, 2) = 768
    gemm32_v6<64><<<dim3(E3 / 512, E / 64, 2), 256>>>(X, Wqkv, qkv, E, E3);

    // 2) Fused attention + cache concat (R10 proven body)
    attn_kernel<<<B * H, 256>>>(kcache, vcache, mask, out_Kc, out_Vc);

    // 3) Output projection: FFMA2 row-split gemm, GK=32 -> (4, 64, 2) = 512
    gemm32_v6<32><<<dim3(E / 512, E / 32, 2), 256>>>(ctx, Wo, out_O, E, E);
}

// round 15
// speedup vs baseline: 1.0464x; 1.0464x over previous
#include <cuda_runtime.h>
#include <cuda_bf16.h>
#include <math.h>

// Problem constants (fixed by the dataset)
#define B   32
#define H   16
#define D   128
#define KV  2048
#define E   2048          // H*D
#define E3  6144          // 3*E
#define KV1 2049          // KV+1
#define KV1P 2052         // KV1 padded (keeps smem 16B-aligned)

// Scratch (device globals: allocation-free rule)
__device__ __align__(16) float g_qkv[B * E3];   // QKV projection result (B, 3E)
__device__ __align__(16) float g_ctx[B * E];    // attention context (B, E)

// ---------------------------------------------------------------------------
// Init: seed atomic-accumulated outputs with bias; emit mask_new.
// ---------------------------------------------------------------------------
__global__ void init_kernel(const float* __restrict__ bqkv,
                            const float* __restrict__ bo,
                            const float* __restrict__ mask,
                            float* __restrict__ qkv,
                            float* __restrict__ outO,
                            float* __restrict__ outmask)
{
    const int i = blockIdx.x * blockDim.x + threadIdx.x;
    const int stride = gridDim.x * blockDim.x;
    for (int j = i; j < B * E3; j += stride) qkv[j] = bqkv[j % E3];
    for (int j = i; j < B * E;  j += stride) outO[j] = bo[j & (E - 1)];
    for (int j = i; j < B * KV1; j += stride) {
        int b = j / KV1, k = j - b * KV1;
        outmask[j] = (k == KV) ? 1.0f : mask[b * KV + k];
    }
}

// ---------------------------------------------------------------------------
// Split-K skinny GEMM (R10-proven): Y[32, N] += X[32, k-slice] @ W[k-slice, N]
// grid = (N/256, K/GK), 256 threads. Thread = one output column.
// 8 coalesced streaming W loads per k-group, 32 row-accumulators,
// X tile in smem read lane-uniform. atomicAdd epilogue.
// ---------------------------------------------------------------------------
template <int GK>
__global__ void __launch_bounds__(256, 4)
gemm32_v3(const float* __restrict__ X,
          const float* __restrict__ W,
          float* __restrict__ Y,
          int K, int N)
{
    __shared__ __align__(16) float xs[32][GK];

    const int tid = threadIdx.x;
    const int col = blockIdx.x * 256 + tid;
    const int k0  = blockIdx.y * GK;

    // stage X[0:32][k0:k0+GK]
    #pragma unroll
    for (int f = tid; f < 32 * GK / 4; f += 256) {
        const int row = f / (GK / 4);
        const int kq  = f % (GK / 4);
        *(float4*)&xs[row][kq * 4] =
            *(const float4*)(X + (size_t)row * K + k0 + kq * 4);
    }
    __syncthreads();

    float acc[32];
    #pragma unroll
    for (int r = 0; r < 32; r++) acc[r] = 0.f;

    const float* Wp = W + (size_t)k0 * N + col;

    #pragma unroll 2
    for (int kk = 0; kk < GK; kk += 8) {
        float wv[8];
        #pragma unroll
        for (int j = 0; j < 8; j++) wv[j] = __ldcs(Wp + (size_t)(kk + j) * N);
        #pragma unroll
        for (int r = 0; r < 32; r++) {
            const float4 xa = *(const float4*)&xs[r][kk];
            const float4 xb = *(const float4*)&xs[r][kk + 4];
            float a = acc[r];
            a += xa.x * wv[0]; a += xa.y * wv[1];
            a += xa.z * wv[2]; a += xa.w * wv[3];
            a += xb.x * wv[4]; a += xb.y * wv[5];
            a += xb.z * wv[6]; a += xb.w * wv[7];
            acc[r] = a;
        }
    }

    float* Yc = Y + col;
    #pragma unroll
    for (int r = 0; r < 32; r++)
        atomicAdd(Yc + (size_t)r * N, acc[r]);
}

// ---------------------------------------------------------------------------
// Fused attention + KV-cache concat (R10/R8 proven body).
// One block per (b, h). 256 threads.
// ---------------------------------------------------------------------------
__global__ void attn_kernel(const float* __restrict__ kcache,
                            const float* __restrict__ vcache,
                            const float* __restrict__ mask,
                            float* __restrict__ out_Kc,
                            float* __restrict__ out_Vc)
{
    __shared__ __align__(16) float q_sm[D];
    __shared__ __align__(16) float sc[KV1P];
    __shared__ __align__(16) float red[20];
    __shared__ __align__(16) float cpart[8][D];

    const int tid = threadIdx.x;
    const int w   = tid >> 5;
    const int l   = tid & 31;
    const int b   = blockIdx.x >> 4;
    const int h   = blockIdx.x & 15;
    const float scale = 0.08838834764831845f;   // 1/sqrt(128)

    const float* mrow = mask + (size_t)b * KV;

    if (tid < D) q_sm[tid] = g_qkv[(size_t)b * E3 + h * D + tid];
    __syncthreads();

    const float4 qf = *(const float4*)&q_sm[l * 4];

    const size_t bh = (size_t)b * H + h;
    const float4* Kin  = (const float4*)(kcache + bh * KV * D);
    float4*       Kout = (float4*)(out_Kc + bh * (size_t)KV1 * D);

    // ---- Pass 1: scores + Kc copy. Warp w does keys [kb, kb+8) ----
    for (int kb = w * 8; kb < KV; kb += 64) {
        float4 a[8];
        #pragma unroll
        for (int j = 0; j < 8; j++) a[j] = Kin[(size_t)(kb + j) * 32 + l];
        #pragma unroll
        for (int j = 0; j < 8; j++) Kout[(size_t)(kb + j) * 32 + l] = a[j];

        float dd[8];
        #pragma unroll
        for (int j = 0; j < 8; j++)
            dd[j] = a[j].x * qf.x + a[j].y * qf.y + a[j].z * qf.z + a[j].w * qf.w;
        #pragma unroll
        for (int j = 0; j < 8; j++) {
            #pragma unroll
            for (int off = 16; off > 0; off >>= 1)
                dd[j] += __shfl_xor_sync(0xFFFFFFFFu, dd[j], off);
        }
        if (l < 8) {
            float dv = dd[l];
            float m  = mrow[kb + l];
            sc[kb + l] = (m == 0.0f) ? -1e30f : dv * scale;
        }
    }

    // new key: from qkv scratch, also write Kc row 2048
    if (w == 0) {
        float4 kn = *(const float4*)&g_qkv[(size_t)b * E3 + E + h * D + l * 4];
        Kout[(size_t)KV * 32 + l] = kn;
        float dn = kn.x * qf.x + kn.y * qf.y + kn.z * qf.z + kn.w * qf.w;
        #pragma unroll
        for (int off = 16; off > 0; off >>= 1)
            dn += __shfl_xor_sync(0xFFFFFFFFu, dn, off);
        if (l == 0) sc[KV] = dn * scale;   // new token never masked
    }
    __syncthreads();

    // ---- Softmax over sc[0..2048] ----
    float mx = -1e30f;
    for (int k = tid; k < KV1; k += 256) mx = fmaxf(mx, sc[k]);
    #pragma unroll
    for (int off = 16; off > 0; off >>= 1)
        mx = fmaxf(mx, __shfl_xor_sync(0xFFFFFFFFu, mx, off));
    if (l == 0) red[w] = mx;
    __syncthreads();
    if (tid == 0) {
        float m = red[0];
        #pragma unroll
        for (int i = 1; i < 8; i++) m = fmaxf(m, red[i]);
        red[0] = m;
    }
    __syncthreads();
    const float M = red[0];

    float ls = 0.f;
    for (int k = tid; k < KV1; k += 256) {
        float e = __expf(sc[k] - M);
        sc[k] = e;
        ls += e;
    }
    #pragma unroll
    for (int off = 16; off > 0; off >>= 1)
        ls += __shfl_xor_sync(0xFFFFFFFFu, ls, off);
    if (l == 0) red[8 + w] = ls;
    __syncthreads();
    if (tid == 0) {
        float s = 0.f;
        #pragma unroll
        for (int i = 0; i < 8; i++) s += red[8 + i];
        red[16] = 1.0f / s;
    }
    __syncthreads();

    // ---- Pass 2: ctx + Vc copy. Warp w owns keys [w*256, w*256+256) ----
    const float4* Vin  = (const float4*)(vcache + bh * KV * D);
    float4*       Vout = (float4*)(out_Vc + bh * (size_t)KV1 * D);

    float4 acc = make_float4(0.f, 0.f, 0.f, 0.f);
    const int kstart = w * 256;
    for (int k = kstart; k < kstart + 256; k += 8) {
        float4 v[8];
        #pragma unroll
        for (int j = 0; j < 8; j++) v[j] = Vin[(size_t)(k + j) * 32 + l];
        #pragma unroll
        for (int j = 0; j < 8; j++) Vout[(size_t)(k + j) * 32 + l] = v[j];
        #pragma unroll
        for (int j = 0; j < 8; j++) {
            const float p = sc[k + j];
            acc.x += p * v[j].x; acc.y += p * v[j].y;
            acc.z += p * v[j].z; acc.w += p * v[j].w;
        }
    }
    if (w == 7) {
        float4 vn = *(const float4*)&g_qkv[(size_t)b * E3 + 2 * E + h * D + l * 4];
        Vout[(size_t)KV * 32 + l] = vn;
        float p = sc[KV];
        acc.x += p * vn.x; acc.y += p * vn.y; acc.z += p * vn.z; acc.w += p * vn.w;
    }
    *(float4*)&cpart[w][l * 4] = acc;
    __syncthreads();

    if (tid < D) {
        float s = 0.f;
        #pragma unroll
        for (int i = 0; i < 8; i++) s += cpart[i][tid];
        g_ctx[(size_t)b * E + h * D + tid] = s * red[16];
    }
}

// ---------------------------------------------------------------------------
extern "C" void kernel_launch(void* const* d_in, const int* in_sizes, int n_in,
                              void* d_out, int out_size)
{
    const float* X      = (const float*)d_in[0];
    const float* kcache = (const float*)d_in[1];
    const float* vcache = (const float*)d_in[2];
    const float* mask   = (const float*)d_in[3];
    const float* Wqkv   = (const float*)d_in[4];
    const float* bqkv   = (const float*)d_in[5];
    const float* Wo     = (const float*)d_in[6];
    const float* bo     = (const float*)d_in[7];

    float* out_O  = (float*)d_out;                              // (B, 1, E)
    float* out_Kc = out_O  + (size_t)B * E;                     // (B, H, KV1, D)
    float* out_Vc = out_Kc + (size_t)B * H * KV1 * D;           // (B, H, KV1, D)
    float* out_mk = out_Vc + (size_t)B * H * KV1 * D;           // (B, KV1)

    float* qkv;  cudaGetSymbolAddress((void**)&qkv,  g_qkv);
    float* ctx;  cudaGetSymbolAddress((void**)&ctx,  g_ctx);

    // 0) Seed outputs with bias (atomics accumulate on top), emit mask_new
    init_kernel<<<256, 256>>>(bqkv, bo, mask, qkv, out_O, out_mk);

    // 1) QKV projection: GK=32 -> grid (24, 64) = 1536 blocks (~10 CTA/SM)
    gemm32_v3<32><<<dim3(E3 / 256, E / 32), 256>>>(X, Wqkv, qkv, E, E3);

    // 2) Fused attention + cache concat (R10 proven body)
    attn_kernel<<<B * H, 256>>>(kcache, vcache, mask, out_Kc, out_Vc);

    // 3) Output projection: GK=32 -> grid (8, 64) = 512 blocks
    gemm32_v3<32><<<dim3(E / 256, E / 32), 256>>>(ctx, Wo, out_O, E, E);
}